// round 1
// baseline (speedup 1.0000x reference)
#include <cuda_runtime.h>
#include <math.h>

#define NN 50000
#define EE 800000
#define EPE (EE + NN)          // edges + self loops = 850000
#define GG 64
#define NEG_SLOPE 0.2f
#define NBSCAN ((NN + 1023) / 1024)   // 49

// ---------------- scratch (device globals; no allocation allowed) ----------------
__device__ float g_h[(size_t)NN * 256];   // linear-transformed features of current layer
__device__ float g_x1[(size_t)NN * 256];  // layer1 output
__device__ float g_x2[(size_t)NN * 256];  // layer2 output
__device__ float g_as[NN * 4];            // per-node per-head src attention logits
__device__ float g_ad[NN * 4];            // per-node per-head dst attention logits
__device__ int   g_counts[NN];
__device__ int   g_rowstart[NN + 1];
__device__ int   g_cursor[NN];
__device__ int   g_csrc[EPE];
__device__ int   g_bsum[64];

// ---------------- CSR build ----------------
__global__ void k_zero_counts() {
    int i = blockIdx.x * blockDim.x + threadIdx.x;
    if (i < NN) g_counts[i] = 0;
}

__global__ void k_hist(const int* __restrict__ ei) {
    int e = blockIdx.x * blockDim.x + threadIdx.x;
    if (e < EPE) {
        int d = (e < EE) ? ei[EE + e] : (e - EE);
        atomicAdd(&g_counts[d], 1);
    }
}

__global__ void k_scan1() {
    __shared__ int s[1024];
    int t = threadIdx.x, b = blockIdx.x, i = b * 1024 + t;
    int v = (i < NN) ? g_counts[i] : 0;
    s[t] = v;
    __syncthreads();
    for (int off = 1; off < 1024; off <<= 1) {
        int x = (t >= off) ? s[t - off] : 0;
        __syncthreads();
        s[t] += x;
        __syncthreads();
    }
    if (i < NN) g_rowstart[i] = s[t] - v;  // exclusive, pre-block-offset
    if (t == 1023) g_bsum[b] = s[1023];
}

__global__ void k_scan2() {
    if (threadIdx.x == 0) {
        int run = 0;
        for (int b = 0; b < NBSCAN; b++) {
            int t = g_bsum[b];
            g_bsum[b] = run;
            run += t;
        }
        g_rowstart[NN] = run;  // == EPE
    }
}

__global__ void k_scan3() {
    int i = blockIdx.x * 1024 + threadIdx.x;
    if (i < NN) {
        int r = g_rowstart[i] + g_bsum[blockIdx.x];
        g_rowstart[i] = r;
        g_cursor[i] = r;
    }
}

__global__ void k_scatter(const int* __restrict__ ei) {
    int e = blockIdx.x * blockDim.x + threadIdx.x;
    if (e < EPE) {
        int s, d;
        if (e < EE) { s = ei[e]; d = ei[EE + e]; }
        else        { s = e - EE; d = s; }
        int pos = atomicAdd(&g_cursor[d], 1);
        g_csrc[pos] = s;
    }
}

// ---------------- SGEMM: C[M,Nd] = A[M,K] @ B[K,Nd] ----------------
// BM=128, BN=64, BK=16, 256 threads, 8x4 per-thread micro-tile.
#define BM 128
#define BN 64
#define BKK 16
__global__ void __launch_bounds__(256) k_gemm(const float* __restrict__ A,
                                              const float* __restrict__ B,
                                              float* __restrict__ C,
                                              int M, int Nd, int K) {
    __shared__ float As[BKK][BM + 4];
    __shared__ float Bs[BKK][BN];
    int tx = threadIdx.x;
    int bm = blockIdx.y * BM, bn = blockIdx.x * BN;
    int tr = tx >> 4, tc = tx & 15;
    float acc[8][4];
#pragma unroll
    for (int i = 0; i < 8; i++)
#pragma unroll
        for (int j = 0; j < 4; j++) acc[i][j] = 0.f;

    for (int k0 = 0; k0 < K; k0 += BKK) {
#pragma unroll
        for (int u = 0; u < 2; u++) {
            int idx = tx + u * 256;
            int ar = idx >> 2, ac4 = (idx & 3) * 4;
            int row = bm + ar;
            float4 av = (row < M) ? *(const float4*)&A[(size_t)row * K + k0 + ac4]
                                  : make_float4(0.f, 0.f, 0.f, 0.f);
            As[ac4 + 0][ar] = av.x;
            As[ac4 + 1][ar] = av.y;
            As[ac4 + 2][ar] = av.z;
            As[ac4 + 3][ar] = av.w;
        }
        {
            int br = tx >> 4, bc4 = (tx & 15) * 4;
            *(float4*)&Bs[br][bc4] = *(const float4*)&B[(size_t)(k0 + br) * Nd + bn + bc4];
        }
        __syncthreads();
#pragma unroll
        for (int kk = 0; kk < BKK; kk++) {
            float4 a0 = *(float4*)&As[kk][tr * 8];
            float4 a1 = *(float4*)&As[kk][tr * 8 + 4];
            float4 b0 = *(float4*)&Bs[kk][tc * 4];
            float a[8] = {a0.x, a0.y, a0.z, a0.w, a1.x, a1.y, a1.z, a1.w};
            float bb[4] = {b0.x, b0.y, b0.z, b0.w};
#pragma unroll
            for (int i = 0; i < 8; i++)
#pragma unroll
                for (int j = 0; j < 4; j++) acc[i][j] += a[i] * bb[j];
        }
        __syncthreads();
    }
#pragma unroll
    for (int i = 0; i < 8; i++) {
        int row = bm + tr * 8 + i;
        if (row < M)
            *(float4*)&C[(size_t)row * Nd + bn + tc * 4] =
                make_float4(acc[i][0], acc[i][1], acc[i][2], acc[i][3]);
    }
}

// ---------------- per-node attention logits: as[n,h] = <h[n,h,:], a_src[h,:]> ----------------
template <int HEADS, int C>
__global__ void k_alpha(const float* __restrict__ h, const float* __restrict__ asrc,
                        const float* __restrict__ adst) {
    const int FDIM = HEADS * C, CH = FDIM / 32;
    int gw = (blockIdx.x * blockDim.x + threadIdx.x) >> 5;
    int lane = threadIdx.x & 31;
    if (gw >= NN) return;
    int base = lane * CH;
    float ps = 0.f, pd = 0.f;
    const float* hp = h + (size_t)gw * FDIM + base;
#pragma unroll
    for (int k2 = 0; k2 < CH; k2++) {
        float v = hp[k2];
        ps += v * asrc[base + k2];
        pd += v * adst[base + k2];
    }
    const int gsz = C / CH;  // lanes per head
#pragma unroll
    for (int off = gsz >> 1; off > 0; off >>= 1) {
        ps += __shfl_xor_sync(0xffffffffu, ps, off);
        pd += __shfl_xor_sync(0xffffffffu, pd, off);
    }
    if ((lane & (gsz - 1)) == 0) {
        int hd = base / C;
        g_as[gw * HEADS + hd] = ps;
        g_ad[gw * HEADS + hd] = pd;
    }
}

// ---------------- warp-per-dst aggregation: softmax + weighted gather + bias (+ELU) ----------------
template <int HEADS, int C, int DO_ELU>
__global__ void k_agg(const float* __restrict__ h, const float* __restrict__ bias,
                      float* __restrict__ outp) {
    const int FDIM = HEADS * C, CH = FDIM / 32;
    int n = (blockIdx.x * blockDim.x + threadIdx.x) >> 5;
    int lane = threadIdx.x & 31;
    if (n >= NN) return;
    int base = lane * CH;
    int myh = base / C;
    int row = g_rowstart[n];
    int deg = g_rowstart[n + 1] - row;

    float adv[HEADS];
#pragma unroll
    for (int hd = 0; hd < HEADS; hd++) adv[hd] = g_ad[n * HEADS + hd];

    const float NEGI = -1e30f;
    float m[HEADS], s[HEADS];
#pragma unroll
    for (int hd = 0; hd < HEADS; hd++) { m[hd] = NEGI; s[hd] = 0.f; }

    // pass 1: online softmax stats, edges distributed across lanes
    for (int j = lane; j < deg; j += 32) {
        int sn = g_csrc[row + j];
        float av[HEADS];
        if constexpr (HEADS == 4) {
            float4 a4 = *(const float4*)&g_as[sn * 4];
            av[0] = a4.x; av[1] = a4.y; av[2] = a4.z; av[3] = a4.w;
        } else {
            av[0] = g_as[sn];
        }
#pragma unroll
        for (int hd = 0; hd < HEADS; hd++) {
            float e = av[hd] + adv[hd];
            e = e > 0.f ? e : NEG_SLOPE * e;
            float mn = fmaxf(m[hd], e);
            s[hd] = s[hd] * __expf(m[hd] - mn) + __expf(e - mn);
            m[hd] = mn;
        }
    }
    // combine (m,s) across lanes (butterfly -> all lanes converge)
#pragma unroll
    for (int off = 16; off > 0; off >>= 1) {
#pragma unroll
        for (int hd = 0; hd < HEADS; hd++) {
            float mo = __shfl_xor_sync(0xffffffffu, m[hd], off);
            float so = __shfl_xor_sync(0xffffffffu, s[hd], off);
            float mn = fmaxf(m[hd], mo);
            s[hd] = s[hd] * __expf(m[hd] - mn) + so * __expf(mo - mn);
            m[hd] = mn;
        }
    }
    float inv[HEADS];
#pragma unroll
    for (int hd = 0; hd < HEADS; hd++) inv[hd] = 1.f / (s[hd] + 1e-16f);

    // pass 2: whole warp walks each edge, lanes own CH channels
    float acc[CH];
#pragma unroll
    for (int k2 = 0; k2 < CH; k2++) acc[k2] = 0.f;
    float myad = adv[myh], mym = m[myh], myinv = inv[myh];
    for (int j = 0; j < deg; j++) {
        int sn = g_csrc[row + j];
        float av = g_as[sn * HEADS + myh];
        float e = av + myad;
        e = e > 0.f ? e : NEG_SLOPE * e;
        float w = __expf(e - mym) * myinv;
        const float* hp = h + (size_t)sn * FDIM + base;
        if constexpr (CH == 8) {
            float4 v0 = *(const float4*)hp;
            float4 v1 = *(const float4*)(hp + 4);
            acc[0] += w * v0.x; acc[1] += w * v0.y; acc[2] += w * v0.z; acc[3] += w * v0.w;
            acc[4] += w * v1.x; acc[5] += w * v1.y; acc[6] += w * v1.z; acc[7] += w * v1.w;
        } else {
            float2 v0 = *(const float2*)hp;
            acc[0] += w * v0.x; acc[1] += w * v0.y;
        }
    }
    float* op = outp + (size_t)n * FDIM + base;
#pragma unroll
    for (int k2 = 0; k2 < CH; k2++) {
        float v = acc[k2] + bias[base + k2];
        if (DO_ELU) v = v > 0.f ? v : expm1f(v);
        op[k2] = v;
    }
}

// ---------------- global mean pool (batch ids sorted -> binary search per graph) ----------------
__global__ void k_pool(const float* __restrict__ ne, const int* __restrict__ batch,
                       float* __restrict__ ge) {
    __shared__ int slo, shi;
    int g = blockIdx.x;
    if (threadIdx.x == 0) {
        int lo = 0, hi = NN;
        while (lo < hi) { int mid = (lo + hi) >> 1; if (batch[mid] < g) lo = mid + 1; else hi = mid; }
        slo = lo;
        lo = 0; hi = NN;
        while (lo < hi) { int mid = (lo + hi) >> 1; if (batch[mid] < g + 1) lo = mid + 1; else hi = mid; }
        shi = lo;
    }
    __syncthreads();
    int lo = slo, hi = shi;
    int c = threadIdx.x;
    float sum = 0.f;
    for (int n2 = lo; n2 < hi; n2++) sum += ne[(size_t)n2 * 64 + c];
    float cnt = (float)(hi - lo);
    ge[g * 64 + c] = sum / fmaxf(cnt, 1.f);
}

// ---------------- launch ----------------
extern "C" void kernel_launch(void* const* d_in, const int* in_sizes, int n_in,
                              void* d_out, int out_size) {
    const float* x   = (const float*)d_in[0];
    const int*   ei  = (const int*)d_in[1];
    const int*   bat = (const int*)d_in[2];
    const float* W1  = (const float*)d_in[3];
    const float* as1 = (const float*)d_in[4];
    const float* ad1 = (const float*)d_in[5];
    const float* b1  = (const float*)d_in[6];
    const float* W2  = (const float*)d_in[7];
    const float* as2 = (const float*)d_in[8];
    const float* ad2 = (const float*)d_in[9];
    const float* b2  = (const float*)d_in[10];
    const float* W3  = (const float*)d_in[11];
    const float* as3 = (const float*)d_in[12];
    const float* ad3 = (const float*)d_in[13];
    const float* b3  = (const float*)d_in[14];
    float* outp = (float*)d_out;

    float *hbuf, *x1, *x2;
    cudaGetSymbolAddress((void**)&hbuf, g_h);
    cudaGetSymbolAddress((void**)&x1, g_x1);
    cudaGetSymbolAddress((void**)&x2, g_x2);

    const int WBLK = (NN * 32 + 255) / 256;  // warp-per-node grids

    // CSR build (by destination), recomputed every call (deterministic)
    k_zero_counts<<<(NN + 255) / 256, 256>>>();
    k_hist<<<(EPE + 255) / 256, 256>>>(ei);
    k_scan1<<<NBSCAN, 1024>>>();
    k_scan2<<<1, 32>>>();
    k_scan3<<<NBSCAN, 1024>>>();
    k_scatter<<<(EPE + 255) / 256, 256>>>(ei);

    // layer 1: 256 -> 4x64, ELU
    k_gemm<<<dim3(256 / BN, (NN + BM - 1) / BM), 256>>>(x, W1, hbuf, NN, 256, 256);
    k_alpha<4, 64><<<WBLK, 256>>>(hbuf, as1, ad1);
    k_agg<4, 64, 1><<<WBLK, 256>>>(hbuf, b1, x1);

    // layer 2: 256 -> 4x64, ELU
    k_gemm<<<dim3(256 / BN, (NN + BM - 1) / BM), 256>>>(x1, W2, hbuf, NN, 256, 256);
    k_alpha<4, 64><<<WBLK, 256>>>(hbuf, as2, ad2);
    k_agg<4, 64, 1><<<WBLK, 256>>>(hbuf, b2, x2);

    // layer 3: 256 -> 1x64, no ELU, writes node embeddings straight into d_out
    k_gemm<<<dim3(64 / BN, (NN + BM - 1) / BM), 256>>>(x2, W3, hbuf, NN, 64, 256);
    k_alpha<1, 64><<<WBLK, 256>>>(hbuf, as3, ad3);
    k_agg<1, 64, 0><<<WBLK, 256>>>(hbuf, b3, outp);

    // global mean pool -> graph embeddings after node embeddings
    k_pool<<<GG, 64>>>(outp, bat, outp + (size_t)NN * 64);
}